// round 11
// baseline (speedup 1.0000x reference)
#include <cuda_runtime.h>
#include <cuda_bf16.h>
#include <math.h>

// Problem constants (fixed by the reference)
#define N_ 50000
#define E_ 800000
#define HID_ 128
#define NC_ 3
#define EPS_ 1e-16f

// ---------------- scratch (static device globals; no runtime alloc) -------
__device__ float g_h[N_ * 128];
__device__ float g_q[N_ * 128];
__device__ float g_k[N_ * 128];
__device__ float g_v[N_ * 128];
__device__ float g_xr[N_ * 128];
// CSR (built once per launch; edge_index constant across layers)
__device__ int g_start[N_ + 1];
__device__ int g_cur[N_];
__device__ int g_eid[E_];

// ---------------- CSR build kernels ---------------------------------------
__global__ void csr_zero_kernel() {
    int i = blockIdx.x * blockDim.x + threadIdx.x;
    if (i < N_) g_cur[i] = 0;
}

__global__ void csr_hist_kernel(const int* __restrict__ ei) {
    int e = blockIdx.x * blockDim.x + threadIdx.x;
    if (e < E_) atomicAdd(&g_cur[ei[E_ + e]], 1);
}

// single-block exclusive scan over g_cur -> g_start (and reset cursor)
__global__ __launch_bounds__(1024) void csr_scan_kernel() {
    __shared__ int wsum[32];
    __shared__ int s_carry;
    int tid = threadIdx.x;
    if (tid == 0) s_carry = 0;
    __syncthreads();
    for (int base = 0; base < N_; base += 1024) {
        int i = base + tid;
        int x = (i < N_) ? g_cur[i] : 0;
        int v = x;
#pragma unroll
        for (int o = 1; o < 32; o <<= 1) {
            int t = __shfl_up_sync(0xffffffffu, v, o);
            if ((tid & 31) >= o) v += t;
        }
        if ((tid & 31) == 31) wsum[tid >> 5] = v;
        __syncthreads();
        if (tid < 32) {
            int w = wsum[tid];
#pragma unroll
            for (int o = 1; o < 32; o <<= 1) {
                int t = __shfl_up_sync(0xffffffffu, w, o);
                if (tid >= o) w += t;
            }
            wsum[tid] = w;
        }
        __syncthreads();
        int warpoff = (tid >= 32) ? wsum[(tid >> 5) - 1] : 0;
        int incl = v + warpoff;
        int carry = s_carry;
        if (i < N_) {
            int excl = carry + incl - x;
            g_start[i] = excl;
            g_cur[i] = excl;
        }
        __syncthreads();
        if (tid == 1023) s_carry = carry + incl;
        __syncthreads();
    }
    if (tid == 0) g_start[N_] = s_carry;
}

__global__ void csr_fill_kernel(const int* __restrict__ ei) {
    int e = blockIdx.x * blockDim.x + threadIdx.x;
    if (e < E_) {
        int dst = ei[E_ + e];
        int pos = atomicAdd(&g_cur[dst], 1);
        g_eid[pos] = e;
    }
}

// ---------------- kernel: input projection h = x @ Win + bin --------------
__global__ __launch_bounds__(256) void input_proj_kernel(
    const float* __restrict__ x, const float* __restrict__ Win,
    const float* __restrict__ bin_) {
    __shared__ float W_s[5 * 128];
    for (int i = threadIdx.x; i < 5 * 128; i += 256) W_s[i] = Win[i];
    __syncthreads();
    int warp = threadIdx.x >> 5, lane = threadIdx.x & 31;
    int n = blockIdx.x * 8 + warp;
    if (n >= N_) return;
    float xv[5];
#pragma unroll
    for (int d = 0; d < 5; d++) xv[d] = x[n * 5 + d];
    int c0 = lane * 4;
    float4 o;
    float* op = &o.x;
#pragma unroll
    for (int j = 0; j < 4; j++) {
        float acc = bin_[c0 + j];
#pragma unroll
        for (int d = 0; d < 5; d++) acc += xv[d] * W_s[d * 128 + c0 + j];
        op[j] = acc;
    }
    *(float4*)&g_h[(size_t)n * 128 + c0] = o;
}

// ---------------- tf32 helpers --------------------------------------------
__device__ __forceinline__ unsigned to_tf32_bits(float x) {
    unsigned r;
    asm("cvt.rna.tf32.f32 %0, %1;" : "=r"(r) : "f"(x));
    return r;
}

__device__ __forceinline__ void split_tf32(float x, unsigned& hi, unsigned& lo) {
    hi = to_tf32_bits(x);
    lo = to_tf32_bits(x - __uint_as_float(hi));
}

__device__ __forceinline__ void mma_tf32(float c[4], const unsigned a[4],
                                         unsigned b0, unsigned b1) {
    asm volatile(
        "mma.sync.aligned.m16n8k8.row.col.f32.tf32.tf32.f32 "
        "{%0,%1,%2,%3}, {%4,%5,%6,%7}, {%8,%9}, {%0,%1,%2,%3};"
        : "+f"(c[0]), "+f"(c[1]), "+f"(c[2]), "+f"(c[3])
        : "r"(a[0]), "r"(a[1]), "r"(a[2]), "r"(a[3]), "r"(b0), "r"(b1));
}

// ---------------- kernel: quad split-tf32 tensor-core GEMM (R7 variant) ---
#define AS_STRIDE 36    // bank = (4m + k) % 32  -> conflict-free A frags
#define BS_STRIDE 136   // bank = (8k + n) % 32  -> conflict-free B frags
__global__ __launch_bounds__(256) void gemm_tf32_kernel(
    const float* __restrict__ Wq, const float* __restrict__ bq,
    const float* __restrict__ Wk, const float* __restrict__ bk,
    const float* __restrict__ Wv, const float* __restrict__ bv,
    const float* __restrict__ Wsk, const float* __restrict__ bsk) {
    int which = blockIdx.y;
    const float* __restrict__ W = (which == 0) ? Wq : (which == 1) ? Wk
                                : (which == 2) ? Wv : Wsk;
    const float* __restrict__ bias = (which == 0) ? bq : (which == 1) ? bk
                                   : (which == 2) ? bv : bsk;
    float* __restrict__ Out = (which == 0) ? g_q : (which == 1) ? g_k
                            : (which == 2) ? g_v : g_xr;
    const float* __restrict__ A = g_h;

    __shared__ float As[128 * AS_STRIDE];   // raw fp32; split at frag load
    __shared__ float Bs[32 * BS_STRIDE];

    int t = threadIdx.x, warp = t >> 5, lane = t & 31;
    int wm = warp & 3, wn = warp >> 2;        // 4x2 warp grid
    int m0 = blockIdx.x * 128;
    int gid = lane >> 2, tig = lane & 3;      // mma fragment coords

    float acc[2][8][4];
#pragma unroll
    for (int mt = 0; mt < 2; mt++)
#pragma unroll
        for (int nt = 0; nt < 8; nt++)
#pragma unroll
            for (int c = 0; c < 4; c++) acc[mt][nt][c] = 0.f;

    for (int kc = 0; kc < 128; kc += 32) {
#pragma unroll
        for (int i = 0; i < 4; i++) {
            int idx = i * 256 + t;            // 0..1023
            int row = idx >> 3, k4 = (idx & 7) * 4;
            float4 v = make_float4(0.f, 0.f, 0.f, 0.f);
            int gm = m0 + row;
            if (gm < N_) v = *(const float4*)&A[(size_t)gm * 128 + kc + k4];
            *(float4*)&As[row * AS_STRIDE + k4] = v;
        }
#pragma unroll
        for (int i = 0; i < 4; i++) {
            int idx = i * 256 + t;
            int k = idx >> 5, n4 = (idx & 31) * 4;
            float4 v = *(const float4*)&W[(size_t)(kc + k) * 128 + n4];
            *(float4*)&Bs[k * BS_STRIDE + n4] = v;
        }
        __syncthreads();

#pragma unroll
        for (int ks = 0; ks < 32; ks += 8) {
            unsigned ah[2][4], al[2][4];
#pragma unroll
            for (int mt = 0; mt < 2; mt++) {
                int m = wm * 32 + mt * 16 + gid;
                split_tf32(As[m * AS_STRIDE + ks + tig],           ah[mt][0], al[mt][0]);
                split_tf32(As[(m + 8) * AS_STRIDE + ks + tig],     ah[mt][1], al[mt][1]);
                split_tf32(As[m * AS_STRIDE + ks + tig + 4],       ah[mt][2], al[mt][2]);
                split_tf32(As[(m + 8) * AS_STRIDE + ks + tig + 4], ah[mt][3], al[mt][3]);
            }
#pragma unroll
            for (int nh = 0; nh < 2; nh++) {
                unsigned bh_[4][2], bl_[4][2];
#pragma unroll
                for (int j = 0; j < 4; j++) {
                    int nt = nh * 4 + j;
                    int n = wn * 64 + nt * 8 + gid;
                    split_tf32(Bs[(ks + tig) * BS_STRIDE + n],     bh_[j][0], bl_[j][0]);
                    split_tf32(Bs[(ks + tig + 4) * BS_STRIDE + n], bh_[j][1], bl_[j][1]);
                }
#pragma unroll
                for (int mt = 0; mt < 2; mt++)
#pragma unroll
                    for (int j = 0; j < 4; j++) {
                        int nt = nh * 4 + j;
                        mma_tf32(acc[mt][nt], ah[mt], bh_[j][0], bh_[j][1]);
                        mma_tf32(acc[mt][nt], ah[mt], bl_[j][0], bl_[j][1]);
                        mma_tf32(acc[mt][nt], al[mt], bh_[j][0], bh_[j][1]);
                    }
            }
        }
        __syncthreads();
    }

    // epilogue: add bias, store
#pragma unroll
    for (int mt = 0; mt < 2; mt++) {
        int r0 = m0 + wm * 32 + mt * 16 + gid;
#pragma unroll
        for (int nt = 0; nt < 8; nt++) {
            int col = wn * 64 + nt * 8 + tig * 2;
            float b0 = bias[col], b1 = bias[col + 1];
            if (r0 < N_) {
                float2 o0 = make_float2(acc[mt][nt][0] + b0, acc[mt][nt][1] + b1);
                *(float2*)&Out[(size_t)r0 * 128 + col] = o0;
            }
            if (r0 + 8 < N_) {
                float2 o1 = make_float2(acc[mt][nt][2] + b0, acc[mt][nt][3] + b1);
                *(float2*)&Out[(size_t)(r0 + 8) * 128 + col] = o1;
            }
        }
    }
}

// ---------------- kernel: dual-chain online-softmax aggregation -----------
// One warp per dst node; 8-lane groups = one head; lane handles 4 channels.
// Edges processed in PAIRS feeding two independent online-softmax chains
// (merged after the loop) -> half the serial chain, double the MLP.
__global__ __launch_bounds__(256) void agg_kernel(
    const int* __restrict__ ei, const float* __restrict__ ea,
    const float* __restrict__ We_l, const float* __restrict__ Wb_l,
    const float* __restrict__ lng, const float* __restrict__ lnb) {
    __shared__ float We_s[512];
    __shared__ float Wb_s[384];
    __shared__ float g_s[128];
    __shared__ float b_s[128];
    for (int i = threadIdx.x; i < 512; i += 256) We_s[i] = We_l[i];
    for (int i = threadIdx.x; i < 384; i += 256) Wb_s[i] = Wb_l[i];
    for (int i = threadIdx.x; i < 128; i += 256) { g_s[i] = lng[i]; b_s[i] = lnb[i]; }
    __syncthreads();

    int warp = threadIdx.x >> 5, lane = threadIdx.x & 31;
    int n = blockIdx.x * 8 + warp;
    if (n >= N_) return;
    int c0 = lane * 4;

    int start = g_start[n];
    int end = g_start[n + 1];

    float4 qv = *(const float4*)&g_q[(size_t)n * 128 + c0];
    float4 xv4 = *(const float4*)&g_xr[(size_t)n * 128 + c0];  // hoisted
    const float sc = 0.17677669529663687f;  // 1/sqrt(32)

    // two independent online-softmax chains
    float mA = -INFINITY, dA = 0.f, A0 = 0.f, A1 = 0.f, A2 = 0.f, A3 = 0.f;
    float mB = -INFINITY, dB = 0.f, B0 = 0.f, B1 = 0.f, B2 = 0.f, B3 = 0.f;

    // pipeline: data for current pair; indices for next pair
    float4 kA, vA, aA, kB, vB, aB;
    kA = vA = aA = kB = vB = aB = make_float4(0.f, 0.f, 0.f, 0.f);
    int eAn = 0, sAn = 0, eBn = 0, sBn = 0;
    {
        int i = start;
        if (i < end) {
            int e0 = g_eid[i]; int s0 = ei[e0];
            kA = *(const float4*)&g_k[(size_t)s0 * 128 + c0];
            vA = *(const float4*)&g_v[(size_t)s0 * 128 + c0];
            aA = *(const float4*)&ea[(size_t)e0 * 4];
        }
        if (i + 1 < end) {
            int e1 = g_eid[i + 1]; int s1 = ei[e1];
            kB = *(const float4*)&g_k[(size_t)s1 * 128 + c0];
            vB = *(const float4*)&g_v[(size_t)s1 * 128 + c0];
            aB = *(const float4*)&ea[(size_t)e1 * 4];
        }
        if (i + 2 < end) { eAn = g_eid[i + 2]; sAn = ei[eAn]; }
        if (i + 3 < end) { eBn = g_eid[i + 3]; sBn = ei[eBn]; }
    }

    for (int i = start; i < end; i += 2) {
        float4 ka = kA, va = vA, aa = aA;
        float4 kb = kB, vb = vB, ab = aB;
        bool hasB = (i + 1 < end);

        // issue next-pair data loads (indices already resolved)
        if (i + 2 < end) {
            kA = *(const float4*)&g_k[(size_t)sAn * 128 + c0];
            vA = *(const float4*)&g_v[(size_t)sAn * 128 + c0];
            aA = *(const float4*)&ea[(size_t)eAn * 4];
        }
        if (i + 3 < end) {
            kB = *(const float4*)&g_k[(size_t)sBn * 128 + c0];
            vB = *(const float4*)&g_v[(size_t)sBn * 128 + c0];
            aB = *(const float4*)&ea[(size_t)eBn * 4];
        }
        // resolve pair+2 indices
        int eA2 = 0, sA2 = 0, eB2 = 0, sB2 = 0;
        if (i + 4 < end) { eA2 = g_eid[i + 4]; sA2 = ei[eA2]; }
        if (i + 5 < end) { eB2 = g_eid[i + 5]; sB2 = ei[eB2]; }

        // ---- edge A (chain A) ----
        float ea0 = aa.x * We_s[c0 + 0] + aa.y * We_s[128 + c0 + 0] +
                    aa.z * We_s[256 + c0 + 0] + aa.w * We_s[384 + c0 + 0];
        float ea1 = aa.x * We_s[c0 + 1] + aa.y * We_s[128 + c0 + 1] +
                    aa.z * We_s[256 + c0 + 1] + aa.w * We_s[384 + c0 + 1];
        float ea2 = aa.x * We_s[c0 + 2] + aa.y * We_s[128 + c0 + 2] +
                    aa.z * We_s[256 + c0 + 2] + aa.w * We_s[384 + c0 + 2];
        float ea3 = aa.x * We_s[c0 + 3] + aa.y * We_s[128 + c0 + 3] +
                    aa.z * We_s[256 + c0 + 3] + aa.w * We_s[384 + c0 + 3];
        float da = qv.x * (ka.x + ea0) + qv.y * (ka.y + ea1) +
                   qv.z * (ka.z + ea2) + qv.w * (ka.w + ea3);
        // ---- edge B (chain B) ----
        float eb0 = ab.x * We_s[c0 + 0] + ab.y * We_s[128 + c0 + 0] +
                    ab.z * We_s[256 + c0 + 0] + ab.w * We_s[384 + c0 + 0];
        float eb1 = ab.x * We_s[c0 + 1] + ab.y * We_s[128 + c0 + 1] +
                    ab.z * We_s[256 + c0 + 1] + ab.w * We_s[384 + c0 + 1];
        float eb2 = ab.x * We_s[c0 + 2] + ab.y * We_s[128 + c0 + 2] +
                    ab.z * We_s[256 + c0 + 2] + ab.w * We_s[384 + c0 + 2];
        float eb3 = ab.x * We_s[c0 + 3] + ab.y * We_s[128 + c0 + 3] +
                    ab.z * We_s[256 + c0 + 3] + ab.w * We_s[384 + c0 + 3];
        float db = qv.x * (kb.x + eb0) + qv.y * (kb.y + eb1) +
                   qv.z * (kb.z + eb2) + qv.w * (kb.w + eb3);

        // interleaved head reductions (independent)
        da += __shfl_xor_sync(0xffffffffu, da, 1, 8);
        db += __shfl_xor_sync(0xffffffffu, db, 1, 8);
        da += __shfl_xor_sync(0xffffffffu, da, 2, 8);
        db += __shfl_xor_sync(0xffffffffu, db, 2, 8);
        da += __shfl_xor_sync(0xffffffffu, da, 4, 8);
        db += __shfl_xor_sync(0xffffffffu, db, 4, 8);
        float lga = da * sc;
        float lgb = db * sc;

        // chain A update
        {
            float nm = fmaxf(mA, lga);
            float f = __expf(mA - nm);
            float ex = __expf(lga - nm);
            dA = dA * f + ex;
            A0 = A0 * f + ex * (va.x + ea0);
            A1 = A1 * f + ex * (va.y + ea1);
            A2 = A2 * f + ex * (va.z + ea2);
            A3 = A3 * f + ex * (va.w + ea3);
            mA = nm;
        }
        // chain B update (predicated on edge existence)
        if (hasB) {
            float nm = fmaxf(mB, lgb);
            float f = __expf(mB - nm);
            float ex = __expf(lgb - nm);
            dB = dB * f + ex;
            B0 = B0 * f + ex * (vb.x + eb0);
            B1 = B1 * f + ex * (vb.y + eb1);
            B2 = B2 * f + ex * (vb.z + eb2);
            B3 = B3 * f + ex * (vb.w + eb3);
            mB = nm;
        }

        eAn = eA2; sAn = sA2; eBn = eB2; sBn = sB2;
    }

    // merge the two chains (guard degree-0 NaN)
    float nm = fmaxf(mA, mB);
    float fa = __expf(mA - nm), fb = __expf(mB - nm);
    if (nm == -INFINITY) { fa = 0.f; fb = 0.f; }
    float den = dA * fa + dB * fb;
    float a0 = A0 * fa + B0 * fb;
    float a1 = A1 * fa + B1 * fb;
    float a2 = A2 * fa + B2 * fb;
    float a3 = A3 * fa + B3 * fb;

    float inv_d = 1.f / (den + EPS_);
    float o[4] = { a0 * inv_d, a1 * inv_d, a2 * inv_d, a3 * inv_d };

    // ---- fused epilogue: beta skip + ReLU + LayerNorm ----
    float xv[4] = { xv4.x, xv4.y, xv4.z, xv4.w };
    float s = 0.f;
#pragma unroll
    for (int j = 0; j < 4; j++)
        s += o[j] * Wb_s[c0 + j] + xv[j] * Wb_s[128 + c0 + j] +
             (o[j] - xv[j]) * Wb_s[256 + c0 + j];
#pragma unroll
    for (int off = 16; off; off >>= 1) s += __shfl_xor_sync(0xffffffffu, s, off);
    float beta = 1.f / (1.f + expf(-s));
    float r[4];
#pragma unroll
    for (int j = 0; j < 4; j++) {
        float t = beta * xv[j] + (1.f - beta) * o[j];
        r[j] = fmaxf(t, 0.f);
    }
    float sum = r[0] + r[1] + r[2] + r[3];
#pragma unroll
    for (int off = 16; off; off >>= 1) sum += __shfl_xor_sync(0xffffffffu, sum, off);
    float mean = sum * (1.f / 128.f);
    float vs = 0.f;
#pragma unroll
    for (int j = 0; j < 4; j++) { float dd = r[j] - mean; vs += dd * dd; }
#pragma unroll
    for (int off = 16; off; off >>= 1) vs += __shfl_xor_sync(0xffffffffu, vs, off);
    float inv = rsqrtf(vs * (1.f / 128.f) + 1e-5f);
    float4 outv;
    outv.x = (r[0] - mean) * inv * g_s[c0 + 0] + b_s[c0 + 0];
    outv.y = (r[1] - mean) * inv * g_s[c0 + 1] + b_s[c0 + 1];
    outv.z = (r[2] - mean) * inv * g_s[c0 + 2] + b_s[c0 + 2];
    outv.w = (r[3] - mean) * inv * g_s[c0 + 3] + b_s[c0 + 3];
    *(float4*)&g_h[(size_t)n * 128 + c0] = outv;
}

// ---------------- kernel: final head out = h @ Wh + bh --------------------
__global__ __launch_bounds__(256) void final_kernel(
    const float* __restrict__ Wh, const float* __restrict__ bh,
    float* __restrict__ out) {
    __shared__ float W_s[384];
    for (int i = threadIdx.x; i < 384; i += 256) W_s[i] = Wh[i];
    __syncthreads();
    int warp = threadIdx.x >> 5, lane = threadIdx.x & 31;
    int n = blockIdx.x * 8 + warp;
    if (n >= N_) return;
    int c0 = lane * 4;
    float4 hv = *(const float4*)&g_h[(size_t)n * 128 + c0];
    float hr[4] = { hv.x, hv.y, hv.z, hv.w };
#pragma unroll
    for (int cls = 0; cls < NC_; cls++) {
        float p = 0.f;
#pragma unroll
        for (int j = 0; j < 4; j++) p += hr[j] * W_s[(c0 + j) * 3 + cls];
#pragma unroll
        for (int off = 16; off; off >>= 1) p += __shfl_xor_sync(0xffffffffu, p, off);
        if (lane == 0) out[n * 3 + cls] = p + bh[cls];
    }
}

// ---------------- host launcher (pure kernel launches; capture-safe) ------
extern "C" void kernel_launch(void* const* d_in, const int* in_sizes, int n_in,
                              void* d_out, int out_size) {
    const float* x    = (const float*)d_in[0];
    const int*   ei   = (const int*)d_in[1];      // int32 (JAX x64 disabled)
    const float* ea   = (const float*)d_in[2];
    const float* Win  = (const float*)d_in[3];
    const float* bin_ = (const float*)d_in[4];
    const float* Wq   = (const float*)d_in[5];
    const float* bq   = (const float*)d_in[6];
    const float* Wk   = (const float*)d_in[7];
    const float* bk   = (const float*)d_in[8];
    const float* Wv   = (const float*)d_in[9];
    const float* bv   = (const float*)d_in[10];
    const float* We   = (const float*)d_in[11];
    const float* Ws   = (const float*)d_in[12];
    const float* bs   = (const float*)d_in[13];
    const float* Wb   = (const float*)d_in[14];
    const float* lng  = (const float*)d_in[15];
    const float* lnb  = (const float*)d_in[16];
    const float* Wh   = (const float*)d_in[17];
    const float* bh   = (const float*)d_in[18];
    float* out = (float*)d_out;

    const int nodeWarpBlocks = (N_ + 7) / 8;       // 6250
    const int edgeThreadBlocks = (E_ + 255) / 256; // 3125
    const int nodeThreadBlocks = (N_ + 255) / 256; // 196
    const int gemmBlocks = (N_ + 127) / 128;       // 391

    // CSR build (edge_index constant across layers)
    csr_zero_kernel<<<nodeThreadBlocks, 256>>>();
    csr_hist_kernel<<<edgeThreadBlocks, 256>>>(ei);
    csr_scan_kernel<<<1, 1024>>>();
    csr_fill_kernel<<<edgeThreadBlocks, 256>>>(ei);

    input_proj_kernel<<<nodeWarpBlocks, 256>>>(x, Win, bin_);

    for (int l = 0; l < 3; l++) {
        size_t wOff = (size_t)l * 128 * 128;
        size_t bOff = (size_t)l * 128;
        dim3 ggrid(gemmBlocks, 4);
        gemm_tf32_kernel<<<ggrid, 256>>>(Wq + wOff, bq + bOff,
                                         Wk + wOff, bk + bOff,
                                         Wv + wOff, bv + bOff,
                                         Ws + wOff, bs + bOff);
        agg_kernel<<<nodeWarpBlocks, 256>>>(ei, ea, We + (size_t)l * 512,
                                            Wb + (size_t)l * 384,
                                            lng + bOff, lnb + bOff);
    }
    final_kernel<<<nodeWarpBlocks, 256>>>(Wh, bh, out);
}